// round 11
// baseline (speedup 1.0000x reference)
#include <cuda_runtime.h>
#include <cuda_bf16.h>
#include <cfloat>

// Problem constants
constexpr int L   = 8192;   // row length
constexpr int NB  = 65;     // bins / quantile edges
constexpr int NT  = 512;    // threads per block
constexpr int IPT = 16;     // items per thread (NT*IPT == L)
constexpr int ROWS_PER_CTA = 2;

// Skewed (padded) addressing: one pad float per 32 -> strided warp accesses
// land on 32 distinct banks instead of few.
__device__ __forceinline__ int PAD(int i) { return i + (i >> 5); }
constexpr int PADL = L + (L >> 5);          // 8448 floats per buffer

// Shared layout: bufA[PADL] | bufB[PADL] | hist[NB*NB]
constexpr size_t BUF_BYTES  = (size_t)PADL * sizeof(float);
constexpr size_t SMEM_TOTAL = 2 * BUF_BYTES + (size_t)NB * NB * sizeof(unsigned);

// ---------------- bitonic (warp sorts 512, 16/thread), templated stages ------
template <int K, int J>
__device__ __forceinline__ void cross_stage_t(float (&v)[IPT], int lane)
{
    const int  lmask   = J >> 4;
    const bool up      = (lane & lmask) == 0;
    const bool asc     = ((lane << 4) & K) == 0;       // hoisted (K>=32)
    const bool keepMin = (asc == up);
#pragma unroll
    for (int i = 0; i < IPT; ++i) {
        float other = __shfl_xor_sync(0xffffffffu, v[i], lmask);
        v[i] = keepMin ? fminf(v[i], other) : fmaxf(v[i], other);
    }
}

template <int K, int J>
__device__ __forceinline__ void inthread_stage_t(float (&v)[IPT], int lane)
{
    bool ascL = true;
    if constexpr (K >= 32)      ascL = (((lane << 4) & K) == 0);
    else if constexpr (K == 16) ascL = ((lane & 1) == 0);
#pragma unroll
    for (int i = 0; i < IPT; ++i) {
        if ((i & J) != 0) continue;                    // compile-time
        const int q = i | J;
        bool asc;
        if constexpr (K <= 8) asc = ((i & K) == 0);    // compile-time
        else                  asc = ascL;              // per-stage predicate
        float a = v[i], b = v[q];
        float mn = fminf(a, b), mx = fmaxf(a, b);
        v[i] = asc ? mn : mx;
        v[q] = asc ? mx : mn;
    }
}

template <int K>
__device__ __forceinline__ void inthread_tail(float (&v)[IPT], int lane)
{
    if constexpr (K >= 16) inthread_stage_t<K, 8>(v, lane);
    if constexpr (K >= 8)  inthread_stage_t<K, 4>(v, lane);
    if constexpr (K >= 4)  inthread_stage_t<K, 2>(v, lane);
    inthread_stage_t<K, 1>(v, lane);
}

__device__ __forceinline__ void warp_bitonic_512(float (&v)[IPT], int lane)
{
    inthread_tail<2>(v, lane);
    inthread_tail<4>(v, lane);
    inthread_tail<8>(v, lane);
    inthread_tail<16>(v, lane);

    cross_stage_t<32, 16>(v, lane);   inthread_tail<32>(v, lane);
    cross_stage_t<64, 32>(v, lane);
    cross_stage_t<64, 16>(v, lane);   inthread_tail<64>(v, lane);
    cross_stage_t<128, 64>(v, lane);
    cross_stage_t<128, 32>(v, lane);
    cross_stage_t<128, 16>(v, lane);  inthread_tail<128>(v, lane);
    cross_stage_t<256, 128>(v, lane);
    cross_stage_t<256, 64>(v, lane);
    cross_stage_t<256, 32>(v, lane);
    cross_stage_t<256, 16>(v, lane);  inthread_tail<256>(v, lane);
    cross_stage_t<512, 256>(v, lane);
    cross_stage_t<512, 128>(v, lane);
    cross_stage_t<512, 64>(v, lane);
    cross_stage_t<512, 32>(v, lane);
    cross_stage_t<512, 16>(v, lane);  inthread_tail<512>(v, lane);
}

// ------------- merge-path round, 2 independent 8-output chains per thread ----
template <int R>
__device__ __forceinline__ void merge_round(const float* __restrict__ src,
                                            float* __restrict__ dst, int t)
{
    const int pairlen = R << 1;
    const int g0 = t * 8;            // chain 0 output start
    const int g1 = (L / 2) + t * 8;  // chain 1 output start (4096 % pairlen == 0)

    const int pb0 = (g0 / pairlen) * pairlen, o0 = g0 & (pairlen - 1);
    const int pb1 = (g1 / pairlen) * pairlen, o1 = g1 & (pairlen - 1);

    // partition searches (independent -> overlapped latency)
    int alo0 = o0 - R; if (alo0 < 0) alo0 = 0;
    int ahi0 = (o0 < R) ? o0 : R;
    int alo1 = o1 - R; if (alo1 < 0) alo1 = 0;
    int ahi1 = (o1 < R) ? o1 : R;
    while (alo0 < ahi0 || alo1 < ahi1) {
        if (alo0 < ahi0) {
            int amid = (alo0 + ahi0) >> 1;
            if (src[PAD(pb0 + amid)] <= src[PAD(pb0 + R + o0 - 1 - amid)])
                alo0 = amid + 1; else ahi0 = amid;
        }
        if (alo1 < ahi1) {
            int amid = (alo1 + ahi1) >> 1;
            if (src[PAD(pb1 + amid)] <= src[PAD(pb1 + R + o1 - 1 - amid)])
                alo1 = amid + 1; else ahi1 = amid;
        }
    }
    int a0 = alo0, b0 = o0 - alo0;
    int a1 = alo1, b1 = o1 - alo1;

    float av0 = (a0 < R) ? src[PAD(pb0 + a0)]     : FLT_MAX;
    float bv0 = (b0 < R) ? src[PAD(pb0 + R + b0)] : FLT_MAX;
    float av1 = (a1 < R) ? src[PAD(pb1 + a1)]     : FLT_MAX;
    float bv1 = (b1 < R) ? src[PAD(pb1 + R + b1)] : FLT_MAX;
#pragma unroll
    for (int i = 0; i < 8; ++i) {
        bool tA0 = (a0 < R) && (b0 >= R || av0 <= bv0);
        bool tA1 = (a1 < R) && (b1 >= R || av1 <= bv1);
        float ov0 = tA0 ? av0 : bv0;
        float ov1 = tA1 ? av1 : bv1;
        if (tA0) { ++a0; av0 = (a0 < R) ? src[PAD(pb0 + a0)]     : FLT_MAX; }
        else     { ++b0; bv0 = (b0 < R) ? src[PAD(pb0 + R + b0)] : FLT_MAX; }
        if (tA1) { ++a1; av1 = (a1 < R) ? src[PAD(pb1 + a1)]     : FLT_MAX; }
        else     { ++b1; bv1 = (b1 < R) ? src[PAD(pb1 + R + b1)] : FLT_MAX; }
        dst[PAD(g0 + i)] = ov0;
        dst[PAD(g1 + i)] = ov1;
    }
}

// k-th smallest (0-indexed) of the union of two sorted runs in the same padded
// buffer at bases Ab, Bb, each length n.
__device__ __forceinline__ float select2(const float* __restrict__ buf,
                                         int Ab, int Bb, int n, int k)
{
    int ilo = (k + 1 - n > 0) ? (k + 1 - n) : 0;
    int ihi = (k + 1 < n) ? (k + 1) : n;
    for (;;) {
        int i = (ilo + ihi) >> 1;
        int j = k + 1 - i;
        float Aim1 = (i > 0) ? buf[PAD(Ab + i - 1)] : -FLT_MAX;
        float Ai   = (i < n) ? buf[PAD(Ab + i)]     :  FLT_MAX;
        float Bjm1 = (j > 0) ? buf[PAD(Bb + j - 1)] : -FLT_MAX;
        float Bj   = (j < n) ? buf[PAD(Bb + j)]     :  FLT_MAX;
        if (Aim1 > Bj)       ihi = i - 1;
        else if (Bjm1 > Ai)  ilo = i + 1;
        else return fmaxf(Aim1, Bjm1);
    }
}

__global__ __launch_bounds__(NT, 2) void mtf_kernel(const float* __restrict__ x,
                                                    float* __restrict__ out)
{
    extern __shared__ char smem_raw[];
    float*    bufA = reinterpret_cast<float*>(smem_raw);
    float*    bufB = reinterpret_cast<float*>(smem_raw + BUF_BYTES);
    unsigned* hist = reinterpret_cast<unsigned*>(smem_raw + 2 * BUF_BYTES);

    __shared__ float s_eytz[128];    // BFS layout of 127 padded edges
    __shared__ int   s_wmin[16], s_wmax[16], s_wneg[16];
    __shared__ int   s_m, s_neg;

    const int t    = threadIdx.x;
    const int w    = t >> 5;
    const int lane = t & 31;
    const float inv = 1.0f / (float)(L - 1);

    int prevrow = -1;   // row whose histogram awaits writeout (atomics in flight)

#pragma unroll 1
    for (int it = 0; it < ROWS_PER_CTA; ++it) {
        const int row = blockIdx.x * ROWS_PER_CTA + it;
        const float* __restrict__ xr = x + (size_t)row * L;
        const float4* __restrict__ xr4 = reinterpret_cast<const float4*>(xr);

        // ---- Phase 1: load raw row, per-thread scan (LDG + registers only).
        // Runs while prev row's histogram atomics drain underneath.
        float v[IPT];
        int lmin = L, lmax = -1, lneg = 0;
#pragma unroll
        for (int j = 0; j < 4; ++j) {
            float4 p = xr4[t * 4 + j];
            int base = t * IPT + j * 4;
            v[j * 4 + 0] = p.x; v[j * 4 + 1] = p.y;
            v[j * 4 + 2] = p.z; v[j * 4 + 3] = p.w;
#pragma unroll
            for (int c = 0; c < 4; ++c) {
                float val = v[j * 4 + c];
                int idx = base + c;
                if (val != 0.0f) { if (idx < lmin) lmin = idx; if (idx > lmax) lmax = idx; }
                lneg += (val < 0.0f) ? 1 : 0;
            }
        }
        lmin = __reduce_min_sync(0xffffffffu, lmin);
        lmax = __reduce_max_sync(0xffffffffu, lmax);
        lneg = __reduce_add_sync(0xffffffffu, lneg);
        if (lane == 0) { s_wmin[w] = lmin; s_wmax[w] = lmax; s_wneg[w] = lneg; }

        // ---- Phase 2: bitonic sort RAW values (pure ALU/SHFL — the atomic
        // backlog of prev row drains on the idle crossbar during this) ----
        warp_bitonic_512(v, lane);
#pragma unroll
        for (int i = 0; i < IPT; ++i) bufA[PAD(t * IPT + i)] = v[i];

        if (it == 0)   // first iteration: zero hist in the shadow
            for (int i = t; i < NB * NB; i += NT) hist[i] = 0u;

        __syncthreads();            // SYNC A: drains prev atomics + staging

        // ---- Phase 3: warp 0 finalizes scan; everyone merges ----
        if (w == 0 && lane < 16) {
            int a = s_wmin[lane], b = s_wmax[lane], c = s_wneg[lane];
            a = __reduce_min_sync(0x0000ffffu, a);
            b = __reduce_max_sync(0x0000ffffu, b);
            c = __reduce_add_sync(0x0000ffffu, c);
            if (lane == 0) {
                s_m   = (b >= 0) ? (b - a + 1) : 0;
                s_neg = c;
            }
        }

        merge_round<512>(bufA, bufB, t);

        // writeout prev row's histogram + rezero, riding with merge traffic
        if (prevrow >= 0) {
            float* __restrict__ op = out + (size_t)prevrow * NB * NB;
            for (int i = t; i < NB * NB; i += NT) {
                op[i] = (float)hist[i] * inv;
                hist[i] = 0u;
            }
        }
        __syncthreads();            // SYNC 2
        merge_round<1024>(bufB, bufA, t); __syncthreads();   // SYNC 3
        merge_round<2048>(bufA, bufB, t); __syncthreads();   // SYNC 4
        // two sorted runs of 4096 at padded bases 0 and 4096 in bufB

        // ---- Phase 5: Eytzinger nodes select their edge directly.
        // masked[k] = raw_sorted[k] if k < neg_count else raw_sorted[k + zout]
        if (t >= 1 && t < 128) {
            int d    = 31 - __clz((unsigned)t);
            int idx0 = ((((t - (1 << d)) << 1) + 1) << (6 - d)) - 1;
            float q = FLT_MAX;
            if (idx0 < NB) {
                int m = s_m;
                if (m > 0) {
                    const float step = 1.0f / 65.0f;
                    float qlev = (float)idx0 * step;
                    float pos  = qlev * (float)(m - 1);
                    int   lo   = (int)floorf(pos);
                    int   hi   = (int)ceilf(pos);
                    float frac = pos - (float)lo;
                    int neg = s_neg, zout = L - m;
                    int klo = (lo < neg) ? lo : lo + zout;
                    int khi = (hi < neg) ? hi : hi + zout;
                    float vlo = select2(bufB, 0, 4096, 4096, klo);
                    float vhi = (khi == klo) ? vlo
                                             : select2(bufB, 0, 4096, 4096, khi);
                    q = vlo + frac * (vhi - vlo);
                } else {
                    q = 0.0f;
                }
            }
            s_eytz[t] = q;
        }
        __syncthreads();            // SYNC 5

        // ---- Phase 6: bin all values (conflict-free Eytzinger, L1-hot) ----
        int binreg[IPT];
#pragma unroll
        for (int j = 0; j < 4; ++j) {
            float4 p = xr4[t * 4 + j];
            float vals[4] = {p.x, p.y, p.z, p.w};
#pragma unroll
            for (int c = 0; c < 4; ++c) {
                float val = vals[c];
                unsigned node = 1;
#pragma unroll
                for (int s = 0; s < 7; ++s)
                    node = 2u * node + (s_eytz[node] <= val ? 1u : 0u);
                int b = (int)node - 128;
                binreg[j * 4 + c] = (b > NB - 1) ? (NB - 1) : b;
            }
        }

        // boundary bin (next thread's first element) without smem/barrier
        int nextbin = __shfl_down_sync(0xffffffffu, binreg[0], 1);
        if (lane == 31 && t < NT - 1) {
            float val = xr[t * IPT + IPT];
            unsigned node = 1;
#pragma unroll
            for (int s = 0; s < 7; ++s)
                node = 2u * node + (s_eytz[node] <= val ? 1u : 0u);
            int b = (int)node - 128;
            nextbin = (b > NB - 1) ? (NB - 1) : b;
        }

        // ---- Phase 7: transition atomics, fire-and-forget (no barrier) ----
#pragma unroll
        for (int i = 0; i < IPT - 1; ++i)
            atomicAdd(&hist[binreg[i] * NB + binreg[i + 1]], 1u);
        if (t < NT - 1)
            atomicAdd(&hist[binreg[IPT - 1] * NB + nextbin], 1u);

        prevrow = row;
    }

    // ---- Epilogue: drain last row's atomics, write out ----
    __syncthreads();
    {
        float* __restrict__ op = out + (size_t)prevrow * NB * NB;
        for (int i = t; i < NB * NB; i += NT)
            op[i] = (float)hist[i] * inv;
    }
}

extern "C" void kernel_launch(void* const* d_in, const int* in_sizes, int n_in,
                              void* d_out, int out_size)
{
    const float* x = (const float*)d_in[0];
    float* out = (float*)d_out;
    const int rows = in_sizes[0] / L;           // 512*4 = 2048
    const int grid = rows / ROWS_PER_CTA;       // 1024 uniform 2-row CTAs

    cudaFuncSetAttribute(mtf_kernel,
                         cudaFuncAttributeMaxDynamicSharedMemorySize,
                         (int)SMEM_TOTAL);
    mtf_kernel<<<grid, NT, SMEM_TOTAL>>>(x, out);
}

// round 12
// speedup vs baseline: 1.8962x; 1.8962x over previous
#include <cuda_runtime.h>
#include <cuda_bf16.h>
#include <cfloat>

// Problem constants
constexpr int L   = 8192;   // row length
constexpr int NB  = 65;     // bins / quantile edges
constexpr int NT  = 512;    // threads per block
constexpr int IPT = 16;     // items per thread (NT*IPT == L)

// Skewed (padded) addressing: one pad float per 32 -> strided warp accesses
// land on 32 distinct banks instead of few.
__device__ __forceinline__ int PAD(int i) { return i + (i >> 5); }
constexpr int PADL = L + (L >> 5);          // 8448 floats per buffer

// Shared layout: bufA[PADL] | bufB[PADL] | hist[NB*NB]
constexpr size_t BUF_BYTES  = (size_t)PADL * sizeof(float);
constexpr size_t SMEM_TOTAL = 2 * BUF_BYTES + (size_t)NB * NB * sizeof(unsigned);

// ---------------- bitonic (warp sorts 512, 16/thread), templated stages ------
template <int K, int J>
__device__ __forceinline__ void cross_stage_t(float (&v)[IPT], int lane)
{
    const int  lmask   = J >> 4;
    const bool up      = (lane & lmask) == 0;
    const bool asc     = ((lane << 4) & K) == 0;       // hoisted (K>=32)
    const bool keepMin = (asc == up);
#pragma unroll
    for (int i = 0; i < IPT; ++i) {
        float other = __shfl_xor_sync(0xffffffffu, v[i], lmask);
        v[i] = keepMin ? fminf(v[i], other) : fmaxf(v[i], other);
    }
}

template <int K, int J>
__device__ __forceinline__ void inthread_stage_t(float (&v)[IPT], int lane)
{
    bool ascL = true;
    if constexpr (K >= 32)      ascL = (((lane << 4) & K) == 0);
    else if constexpr (K == 16) ascL = ((lane & 1) == 0);
#pragma unroll
    for (int i = 0; i < IPT; ++i) {
        if ((i & J) != 0) continue;                    // compile-time
        const int q = i | J;
        bool asc;
        if constexpr (K <= 8) asc = ((i & K) == 0);    // compile-time
        else                  asc = ascL;              // per-stage predicate
        float a = v[i], b = v[q];
        float mn = fminf(a, b), mx = fmaxf(a, b);
        v[i] = asc ? mn : mx;
        v[q] = asc ? mx : mn;
    }
}

template <int K>
__device__ __forceinline__ void inthread_tail(float (&v)[IPT], int lane)
{
    if constexpr (K >= 16) inthread_stage_t<K, 8>(v, lane);
    if constexpr (K >= 8)  inthread_stage_t<K, 4>(v, lane);
    if constexpr (K >= 4)  inthread_stage_t<K, 2>(v, lane);
    inthread_stage_t<K, 1>(v, lane);
}

__device__ __forceinline__ void warp_bitonic_512(float (&v)[IPT], int lane)
{
    inthread_tail<2>(v, lane);
    inthread_tail<4>(v, lane);
    inthread_tail<8>(v, lane);
    inthread_tail<16>(v, lane);

    cross_stage_t<32, 16>(v, lane);   inthread_tail<32>(v, lane);
    cross_stage_t<64, 32>(v, lane);
    cross_stage_t<64, 16>(v, lane);   inthread_tail<64>(v, lane);
    cross_stage_t<128, 64>(v, lane);
    cross_stage_t<128, 32>(v, lane);
    cross_stage_t<128, 16>(v, lane);  inthread_tail<128>(v, lane);
    cross_stage_t<256, 128>(v, lane);
    cross_stage_t<256, 64>(v, lane);
    cross_stage_t<256, 32>(v, lane);
    cross_stage_t<256, 16>(v, lane);  inthread_tail<256>(v, lane);
    cross_stage_t<512, 256>(v, lane);
    cross_stage_t<512, 128>(v, lane);
    cross_stage_t<512, 64>(v, lane);
    cross_stage_t<512, 32>(v, lane);
    cross_stage_t<512, 16>(v, lane);  inthread_tail<512>(v, lane);
}

// ------------- merge-path round, 2 independent 8-output chains per thread ----
template <int R>
__device__ __forceinline__ void merge_round(const float* __restrict__ src,
                                            float* __restrict__ dst, int t)
{
    const int pairlen = R << 1;
    const int g0 = t * 8;            // chain 0 output start
    const int g1 = (L / 2) + t * 8;  // chain 1 output start (4096 % pairlen == 0)

    const int pb0 = (g0 / pairlen) * pairlen, o0 = g0 & (pairlen - 1);
    const int pb1 = (g1 / pairlen) * pairlen, o1 = g1 & (pairlen - 1);

    // partition searches (independent -> overlapped latency)
    int alo0 = o0 - R; if (alo0 < 0) alo0 = 0;
    int ahi0 = (o0 < R) ? o0 : R;
    int alo1 = o1 - R; if (alo1 < 0) alo1 = 0;
    int ahi1 = (o1 < R) ? o1 : R;
    while (alo0 < ahi0 || alo1 < ahi1) {
        if (alo0 < ahi0) {
            int amid = (alo0 + ahi0) >> 1;
            if (src[PAD(pb0 + amid)] <= src[PAD(pb0 + R + o0 - 1 - amid)])
                alo0 = amid + 1; else ahi0 = amid;
        }
        if (alo1 < ahi1) {
            int amid = (alo1 + ahi1) >> 1;
            if (src[PAD(pb1 + amid)] <= src[PAD(pb1 + R + o1 - 1 - amid)])
                alo1 = amid + 1; else ahi1 = amid;
        }
    }
    int a0 = alo0, b0 = o0 - alo0;
    int a1 = alo1, b1 = o1 - alo1;

    float av0 = (a0 < R) ? src[PAD(pb0 + a0)]     : FLT_MAX;
    float bv0 = (b0 < R) ? src[PAD(pb0 + R + b0)] : FLT_MAX;
    float av1 = (a1 < R) ? src[PAD(pb1 + a1)]     : FLT_MAX;
    float bv1 = (b1 < R) ? src[PAD(pb1 + R + b1)] : FLT_MAX;
#pragma unroll
    for (int i = 0; i < 8; ++i) {
        bool tA0 = (a0 < R) && (b0 >= R || av0 <= bv0);
        bool tA1 = (a1 < R) && (b1 >= R || av1 <= bv1);
        float ov0 = tA0 ? av0 : bv0;
        float ov1 = tA1 ? av1 : bv1;
        if (tA0) { ++a0; av0 = (a0 < R) ? src[PAD(pb0 + a0)]     : FLT_MAX; }
        else     { ++b0; bv0 = (b0 < R) ? src[PAD(pb0 + R + b0)] : FLT_MAX; }
        if (tA1) { ++a1; av1 = (a1 < R) ? src[PAD(pb1 + a1)]     : FLT_MAX; }
        else     { ++b1; bv1 = (b1 < R) ? src[PAD(pb1 + R + b1)] : FLT_MAX; }
        dst[PAD(g0 + i)] = ov0;
        dst[PAD(g1 + i)] = ov1;
    }
}

// k-th smallest (0-indexed) of the union of two sorted runs in the same padded
// buffer at bases Ab, Bb, each length n.
__device__ __forceinline__ float select2(const float* __restrict__ buf,
                                         int Ab, int Bb, int n, int k)
{
    int ilo = (k + 1 - n > 0) ? (k + 1 - n) : 0;
    int ihi = (k + 1 < n) ? (k + 1) : n;
    for (;;) {
        int i = (ilo + ihi) >> 1;
        int j = k + 1 - i;
        float Aim1 = (i > 0) ? buf[PAD(Ab + i - 1)] : -FLT_MAX;
        float Ai   = (i < n) ? buf[PAD(Ab + i)]     :  FLT_MAX;
        float Bjm1 = (j > 0) ? buf[PAD(Bb + j - 1)] : -FLT_MAX;
        float Bj   = (j < n) ? buf[PAD(Bb + j)]     :  FLT_MAX;
        if (Aim1 > Bj)       ihi = i - 1;
        else if (Bjm1 > Ai)  ilo = i + 1;
        else return fmaxf(Aim1, Bjm1);
    }
}

__global__ __launch_bounds__(NT, 2) void mtf_kernel(const float* __restrict__ x,
                                                    float* __restrict__ out)
{
    extern __shared__ char smem_raw[];
    float*    bufA = reinterpret_cast<float*>(smem_raw);
    float*    bufB = reinterpret_cast<float*>(smem_raw + BUF_BYTES);
    unsigned* hist = reinterpret_cast<unsigned*>(smem_raw + 2 * BUF_BYTES);

    __shared__ float s_eytz[128];    // BFS layout of 127 padded edges
    __shared__ int   s_wmin[16], s_wmax[16], s_wneg[16];
    __shared__ int   s_m, s_neg;

    const int row  = blockIdx.x;
    const int t    = threadIdx.x;
    const int w    = t >> 5;
    const int lane = t & 31;

    const float* __restrict__ xr = x + (size_t)row * L;
    const float4* __restrict__ xr4 = reinterpret_cast<const float4*>(xr);

    // ---- Phase 1: load raw row, per-thread scan (registers only) ----
    float v[IPT];
    int lmin = L, lmax = -1, lneg = 0;
#pragma unroll
    for (int j = 0; j < 4; ++j) {
        float4 p = xr4[t * 4 + j];
        int base = t * IPT + j * 4;
        v[j * 4 + 0] = p.x; v[j * 4 + 1] = p.y;
        v[j * 4 + 2] = p.z; v[j * 4 + 3] = p.w;
#pragma unroll
        for (int c = 0; c < 4; ++c) {
            float val = v[j * 4 + c];
            int idx = base + c;
            if (val != 0.0f) { if (idx < lmin) lmin = idx; if (idx > lmax) lmax = idx; }
            lneg += (val < 0.0f) ? 1 : 0;
        }
    }
    lmin = __reduce_min_sync(0xffffffffu, lmin);
    lmax = __reduce_max_sync(0xffffffffu, lmax);
    lneg = __reduce_add_sync(0xffffffffu, lneg);
    if (lane == 0) { s_wmin[w] = lmin; s_wmax[w] = lmax; s_wneg[w] = lneg; }

    // ---- Phase 2: bitonic sort RAW values (ALU/SHFL only, no mask pass) ----
    warp_bitonic_512(v, lane);
#pragma unroll
    for (int i = 0; i < IPT; ++i) bufA[PAD(t * IPT + i)] = v[i];   // conflict-free

    // shadow work before the barrier: vectorized hist zeroing + eytz prefill
    {
        uint4 z4 = make_uint4(0u, 0u, 0u, 0u);
        uint4* h4 = reinterpret_cast<uint4*>(hist);
        for (int i = t; i < (NB * NB) / 4; i += NT) h4[i] = z4;   // 1056 uint4
        if (t == 0) hist[NB * NB - 1] = 0u;                        // tail word
        if (t >= 1 && t < 128) s_eytz[t] = FLT_MAX;                // pad nodes
    }
    __syncthreads();                             // SYNC 1

    // ---- Phase 3: warp 0 finalizes the scan while everyone merges ----
    if (w == 0 && lane < 16) {
        int a = s_wmin[lane], b = s_wmax[lane], c = s_wneg[lane];
        a = __reduce_min_sync(0x0000ffffu, a);
        b = __reduce_max_sync(0x0000ffffu, b);
        c = __reduce_add_sync(0x0000ffffu, c);
        if (lane == 0) {
            s_m   = (b >= 0) ? (b - a + 1) : 0;
            s_neg = c;
        }
    }

    // ---- Phase 4: three merge rounds: 512 -> 1024 -> 2048 -> 4096 ----
    merge_round<512>(bufA, bufB, t);  __syncthreads();   // SYNC 2
    merge_round<1024>(bufB, bufA, t); __syncthreads();   // SYNC 3
    merge_round<2048>(bufA, bufB, t); __syncthreads();   // SYNC 4
    // two sorted runs of 4096 at padded bases 0 and 4096 in bufB

    // ---- Phase 5: distributed quantile selection, ONE select2 per thread.
    // Thread t<130: edge e = t>>1, which = t&1 (0 -> lo rank, 1 -> hi rank).
    // Partner values combine via shfl (pairs are intra-warp: 2e is even).
    // Combiner writes the edge straight into its Eytzinger node.
    if (t < 130) {
        const int e     = t >> 1;
        const int which = t & 1;
        const int m     = s_m;
        float q = 0.0f;
        float frac = 0.0f;
        float val  = 0.0f;
        int   samerank = 1;
        if (m > 0) {
            const float step = 1.0f / 65.0f;
            float qlev = (float)e * step;
            float pos  = qlev * (float)(m - 1);
            int   lo   = (int)floorf(pos);
            int   hi   = (int)ceilf(pos);
            frac = pos - (float)lo;
            samerank = (hi == lo);
            int r    = which ? hi : lo;
            int neg  = s_neg, zout = L - m;
            int k    = (r < neg) ? r : r + zout;
            val = select2(bufB, 0, 4096, 4096, k);
        }
        const unsigned shmask = (w < 4) ? 0xffffffffu : 0x3u;  // warp 4: lanes 0,1
        float vhi = __shfl_down_sync(shmask, val, 1);
        if (which == 0) {
            if (m > 0) {
                float vlo = val;
                if (samerank) vhi = vlo;
                q = vlo + frac * (vhi - vlo);
            }
            // inverse BFS mapping: e -> tree node
            int z    = __ffs(e + 1) - 1;         // trailing zeros of (e+1)
            int d    = 6 - z;
            int jj   = (((e + 1) >> z) - 1) >> 1;
            s_eytz[(1 << d) + jj] = q;
        }
    }
    __syncthreads();                             // SYNC 5

    // ---- Phase 6: bin all values (conflict-free Eytzinger, L1-hot reload) ----
    int binreg[IPT];
#pragma unroll
    for (int j = 0; j < 4; ++j) {
        float4 p = xr4[t * 4 + j];
        float vals[4] = {p.x, p.y, p.z, p.w};
#pragma unroll
        for (int c = 0; c < 4; ++c) {
            float val = vals[c];
            unsigned node = 1;
#pragma unroll
            for (int s = 0; s < 7; ++s)
                node = 2u * node + (s_eytz[node] <= val ? 1u : 0u);
            int b = (int)node - 128;             // count of edges <= val
            binreg[j * 4 + c] = (b > NB - 1) ? (NB - 1) : b;
        }
    }

    // boundary bin (next thread's first element) without smem/barrier
    int nextbin = __shfl_down_sync(0xffffffffu, binreg[0], 1);
    if (lane == 31 && t < NT - 1) {
        float val = xr[t * IPT + IPT];           // L1-hot scalar load
        unsigned node = 1;
#pragma unroll
        for (int s = 0; s < 7; ++s)
            node = 2u * node + (s_eytz[node] <= val ? 1u : 0u);
        int b = (int)node - 128;
        nextbin = (b > NB - 1) ? (NB - 1) : b;
    }

    // ---- Phase 7: transition histogram (shared atomics) ----
#pragma unroll
    for (int i = 0; i < IPT - 1; ++i)
        atomicAdd(&hist[binreg[i] * NB + binreg[i + 1]], 1u);
    if (t < NT - 1)
        atomicAdd(&hist[binreg[IPT - 1] * NB + nextbin], 1u);
    __syncthreads();                             // SYNC 6

    // ---- Phase 8: normalize + store ----
    const float inv = 1.0f / (float)(L - 1);
    float* __restrict__ outr = out + (size_t)row * NB * NB;
    for (int i = t; i < NB * NB; i += NT)
        outr[i] = (float)hist[i] * inv;
}

extern "C" void kernel_launch(void* const* d_in, const int* in_sizes, int n_in,
                              void* d_out, int out_size)
{
    const float* x = (const float*)d_in[0];
    float* out = (float*)d_out;
    const int rows = in_sizes[0] / L;   // 512*4 = 2048

    cudaFuncSetAttribute(mtf_kernel,
                         cudaFuncAttributeMaxDynamicSharedMemorySize,
                         (int)SMEM_TOTAL);
    mtf_kernel<<<rows, NT, SMEM_TOTAL>>>(x, out);
}

// round 13
// speedup vs baseline: 1.9645x; 1.0360x over previous
#include <cuda_runtime.h>
#include <cuda_bf16.h>
#include <cfloat>

// Problem constants
constexpr int L   = 8192;   // row length
constexpr int NB  = 65;     // bins / quantile edges
constexpr int NT  = 512;    // threads per block
constexpr int IPT = 16;     // items per thread (NT*IPT == L)

// Skewed (padded) addressing: one pad float per 32 -> strided warp accesses
// land on 32 distinct banks instead of few.
__device__ __forceinline__ int PAD(int i) { return i + (i >> 5); }
constexpr int PADL = L + (L >> 5);          // 8448 floats per buffer

// Shared layout: bufA[PADL] | bufB[PADL] | hist[NB*NB]
constexpr size_t BUF_BYTES  = (size_t)PADL * sizeof(float);
constexpr size_t SMEM_TOTAL = 2 * BUF_BYTES + (size_t)NB * NB * sizeof(unsigned);

// ---------------- bitonic (warp sorts 512, 16/thread), templated stages ------
template <int K, int J>
__device__ __forceinline__ void cross_stage_t(float (&v)[IPT], int lane)
{
    const int  lmask   = J >> 4;
    const bool up      = (lane & lmask) == 0;
    const bool asc     = ((lane << 4) & K) == 0;       // hoisted (K>=32)
    const bool keepMin = (asc == up);
#pragma unroll
    for (int i = 0; i < IPT; ++i) {
        float other = __shfl_xor_sync(0xffffffffu, v[i], lmask);
        v[i] = keepMin ? fminf(v[i], other) : fmaxf(v[i], other);
    }
}

template <int K, int J>
__device__ __forceinline__ void inthread_stage_t(float (&v)[IPT], int lane)
{
    bool ascL = true;
    if constexpr (K >= 32)      ascL = (((lane << 4) & K) == 0);
    else if constexpr (K == 16) ascL = ((lane & 1) == 0);
#pragma unroll
    for (int i = 0; i < IPT; ++i) {
        if ((i & J) != 0) continue;                    // compile-time
        const int q = i | J;
        bool asc;
        if constexpr (K <= 8) asc = ((i & K) == 0);    // compile-time
        else                  asc = ascL;              // per-stage predicate
        float a = v[i], b = v[q];
        float mn = fminf(a, b), mx = fmaxf(a, b);
        v[i] = asc ? mn : mx;
        v[q] = asc ? mx : mn;
    }
}

template <int K>
__device__ __forceinline__ void inthread_tail(float (&v)[IPT], int lane)
{
    if constexpr (K >= 16) inthread_stage_t<K, 8>(v, lane);
    if constexpr (K >= 8)  inthread_stage_t<K, 4>(v, lane);
    if constexpr (K >= 4)  inthread_stage_t<K, 2>(v, lane);
    inthread_stage_t<K, 1>(v, lane);
}

__device__ __forceinline__ void warp_bitonic_512(float (&v)[IPT], int lane)
{
    inthread_tail<2>(v, lane);
    inthread_tail<4>(v, lane);
    inthread_tail<8>(v, lane);
    inthread_tail<16>(v, lane);

    cross_stage_t<32, 16>(v, lane);   inthread_tail<32>(v, lane);
    cross_stage_t<64, 32>(v, lane);
    cross_stage_t<64, 16>(v, lane);   inthread_tail<64>(v, lane);
    cross_stage_t<128, 64>(v, lane);
    cross_stage_t<128, 32>(v, lane);
    cross_stage_t<128, 16>(v, lane);  inthread_tail<128>(v, lane);
    cross_stage_t<256, 128>(v, lane);
    cross_stage_t<256, 64>(v, lane);
    cross_stage_t<256, 32>(v, lane);
    cross_stage_t<256, 16>(v, lane);  inthread_tail<256>(v, lane);
    cross_stage_t<512, 256>(v, lane);
    cross_stage_t<512, 128>(v, lane);
    cross_stage_t<512, 64>(v, lane);
    cross_stage_t<512, 32>(v, lane);
    cross_stage_t<512, 16>(v, lane);  inthread_tail<512>(v, lane);
}

// ------------- merge-path round, 2 independent 8-output chains per thread ----
// Fixed-depth branchless partitions (no warp divergence); merge compare relies
// on FLT_MAX stream sentinels (FLT_MAX cannot occur in the data).
template <int R>
__device__ __forceinline__ void merge_round(const float* __restrict__ src,
                                            float* __restrict__ dst, int t)
{
    constexpr int STEPS = (R == 512) ? 10 : (R == 1024) ? 11 : 12;
    const int pairlen = R << 1;
    const int g0 = t * 8;            // chain 0 output start
    const int g1 = (L / 2) + t * 8;  // chain 1 output start (4096 % pairlen == 0)

    const int pb0 = (g0 / pairlen) * pairlen, o0 = g0 & (pairlen - 1);
    const int pb1 = (g1 / pairlen) * pairlen, o1 = g1 & (pairlen - 1);

    int lo0 = (o0 - R > 0) ? o0 - R : 0;
    int hi0 = (o0 < R) ? o0 : R;
    int lo1 = (o1 - R > 0) ? o1 - R : 0;
    int hi1 = (o1 < R) ? o1 : R;
#pragma unroll
    for (int s = 0; s < STEPS; ++s) {
        int mid0 = (lo0 + hi0) >> 1;
        int mid1 = (lo1 + hi1) >> 1;
        bool c0 = (src[PAD(pb0 + mid0)] <= src[PAD(pb0 + R + o0 - 1 - mid0)])
                  && (lo0 < hi0);
        bool c1 = (src[PAD(pb1 + mid1)] <= src[PAD(pb1 + R + o1 - 1 - mid1)])
                  && (lo1 < hi1);
        lo0 = c0 ? mid0 + 1 : lo0;   hi0 = c0 ? hi0 : mid0;
        lo1 = c1 ? mid1 + 1 : lo1;   hi1 = c1 ? hi1 : mid1;
    }
    int a0 = lo0, b0 = o0 - lo0;
    int a1 = lo1, b1 = o1 - lo1;

    float av0 = (a0 < R) ? src[PAD(pb0 + a0)]     : FLT_MAX;
    float bv0 = (b0 < R) ? src[PAD(pb0 + R + b0)] : FLT_MAX;
    float av1 = (a1 < R) ? src[PAD(pb1 + a1)]     : FLT_MAX;
    float bv1 = (b1 < R) ? src[PAD(pb1 + R + b1)] : FLT_MAX;
#pragma unroll
    for (int i = 0; i < 8; ++i) {
        bool tA0 = (av0 <= bv0);     // exhausted side holds FLT_MAX
        bool tA1 = (av1 <= bv1);
        float ov0 = tA0 ? av0 : bv0;
        float ov1 = tA1 ? av1 : bv1;
        if (tA0) { ++a0; av0 = (a0 < R) ? src[PAD(pb0 + a0)]     : FLT_MAX; }
        else     { ++b0; bv0 = (b0 < R) ? src[PAD(pb0 + R + b0)] : FLT_MAX; }
        if (tA1) { ++a1; av1 = (a1 < R) ? src[PAD(pb1 + a1)]     : FLT_MAX; }
        else     { ++b1; bv1 = (b1 < R) ? src[PAD(pb1 + R + b1)] : FLT_MAX; }
        dst[PAD(g0 + i)] = ov0;
        dst[PAD(g1 + i)] = ov1;
    }
}

// k-th smallest (0-indexed) of the union of two sorted runs in the same padded
// buffer at bases Ab, Bb, each length n.
__device__ __forceinline__ float select2(const float* __restrict__ buf,
                                         int Ab, int Bb, int n, int k)
{
    int ilo = (k + 1 - n > 0) ? (k + 1 - n) : 0;
    int ihi = (k + 1 < n) ? (k + 1) : n;
    for (;;) {
        int i = (ilo + ihi) >> 1;
        int j = k + 1 - i;
        float Aim1 = (i > 0) ? buf[PAD(Ab + i - 1)] : -FLT_MAX;
        float Ai   = (i < n) ? buf[PAD(Ab + i)]     :  FLT_MAX;
        float Bjm1 = (j > 0) ? buf[PAD(Bb + j - 1)] : -FLT_MAX;
        float Bj   = (j < n) ? buf[PAD(Bb + j)]     :  FLT_MAX;
        if (Aim1 > Bj)       ihi = i - 1;
        else if (Bjm1 > Ai)  ilo = i + 1;
        else return fmaxf(Aim1, Bjm1);
    }
}

__global__ __launch_bounds__(NT, 2) void mtf_kernel(const float* __restrict__ x,
                                                    float* __restrict__ out)
{
    extern __shared__ char smem_raw[];
    float*    bufA = reinterpret_cast<float*>(smem_raw);
    float*    bufB = reinterpret_cast<float*>(smem_raw + BUF_BYTES);
    unsigned* hist = reinterpret_cast<unsigned*>(smem_raw + 2 * BUF_BYTES);

    __shared__ float s_eytz[128];    // BFS layout of 127 padded edges
    __shared__ int   s_wmin[16], s_wmax[16], s_wneg[16];
    __shared__ int   s_m, s_neg;

    const int row  = blockIdx.x;
    const int t    = threadIdx.x;
    const int w    = t >> 5;
    const int lane = t & 31;

    const float* __restrict__ xr = x + (size_t)row * L;
    const float4* __restrict__ xr4 = reinterpret_cast<const float4*>(xr);

    // ---- Phase 1: load raw row, per-thread scan (registers only) ----
    float v[IPT];
    int lmin = L, lmax = -1, lneg = 0;
#pragma unroll
    for (int j = 0; j < 4; ++j) {
        float4 p = xr4[t * 4 + j];
        int base = t * IPT + j * 4;
        v[j * 4 + 0] = p.x; v[j * 4 + 1] = p.y;
        v[j * 4 + 2] = p.z; v[j * 4 + 3] = p.w;
#pragma unroll
        for (int c = 0; c < 4; ++c) {
            float val = v[j * 4 + c];
            int idx = base + c;
            if (val != 0.0f) { if (idx < lmin) lmin = idx; if (idx > lmax) lmax = idx; }
            lneg += (val < 0.0f) ? 1 : 0;
        }
    }
    lmin = __reduce_min_sync(0xffffffffu, lmin);
    lmax = __reduce_max_sync(0xffffffffu, lmax);
    lneg = __reduce_add_sync(0xffffffffu, lneg);
    if (lane == 0) { s_wmin[w] = lmin; s_wmax[w] = lmax; s_wneg[w] = lneg; }

    // ---- Phase 2: bitonic sort RAW values (ALU/SHFL only, no mask pass) ----
    warp_bitonic_512(v, lane);
#pragma unroll
    for (int i = 0; i < IPT; ++i) bufA[PAD(t * IPT + i)] = v[i];   // conflict-free

    // shadow work before the barrier: vectorized hist zeroing + eytz prefill
    {
        uint4 z4 = make_uint4(0u, 0u, 0u, 0u);
        uint4* h4 = reinterpret_cast<uint4*>(hist);
        for (int i = t; i < (NB * NB) / 4; i += NT) h4[i] = z4;   // 1056 uint4
        if (t == 0) hist[NB * NB - 1] = 0u;                        // tail word
        if (t >= 1 && t < 128) s_eytz[t] = FLT_MAX;                // pad nodes
    }
    __syncthreads();                             // SYNC 1

    // ---- Phase 3: warp 0 finalizes the scan while everyone merges ----
    if (w == 0 && lane < 16) {
        int a = s_wmin[lane], b = s_wmax[lane], c = s_wneg[lane];
        a = __reduce_min_sync(0x0000ffffu, a);
        b = __reduce_max_sync(0x0000ffffu, b);
        c = __reduce_add_sync(0x0000ffffu, c);
        if (lane == 0) {
            s_m   = (b >= 0) ? (b - a + 1) : 0;
            s_neg = c;
        }
    }

    // ---- Phase 4: three merge rounds: 512 -> 1024 -> 2048 -> 4096 ----
    merge_round<512>(bufA, bufB, t);  __syncthreads();   // SYNC 2
    merge_round<1024>(bufB, bufA, t); __syncthreads();   // SYNC 3
    merge_round<2048>(bufA, bufB, t); __syncthreads();   // SYNC 4
    // two sorted runs of 4096 at padded bases 0 and 4096 in bufB

    // ---- Phase 5: distributed quantile selection, ONE select2 per thread.
    // Thread t<130: edge e = t>>1, which = t&1 (0 -> lo rank, 1 -> hi rank).
    // Partner values combine via shfl (pairs are intra-warp: 2e is even).
    // Combiner writes the edge straight into its Eytzinger node.
    if (t < 130) {
        const int e     = t >> 1;
        const int which = t & 1;
        const int m     = s_m;
        float q = 0.0f;
        float frac = 0.0f;
        float val  = 0.0f;
        int   samerank = 1;
        if (m > 0) {
            const float step = 1.0f / 65.0f;
            float qlev = (float)e * step;
            float pos  = qlev * (float)(m - 1);
            int   lo   = (int)floorf(pos);
            int   hi   = (int)ceilf(pos);
            frac = pos - (float)lo;
            samerank = (hi == lo);
            int r    = which ? hi : lo;
            int neg  = s_neg, zout = L - m;
            int k    = (r < neg) ? r : r + zout;
            val = select2(bufB, 0, 4096, 4096, k);
        }
        const unsigned shmask = (w < 4) ? 0xffffffffu : 0x3u;  // warp 4: lanes 0,1
        float vhi = __shfl_down_sync(shmask, val, 1);
        if (which == 0) {
            if (m > 0) {
                float vlo = val;
                if (samerank) vhi = vlo;
                q = vlo + frac * (vhi - vlo);
            }
            // inverse BFS mapping: e -> tree node
            int z    = __ffs(e + 1) - 1;         // trailing zeros of (e+1)
            int d    = 6 - z;
            int jj   = (((e + 1) >> z) - 1) >> 1;
            s_eytz[(1 << d) + jj] = q;
        }
    }
    __syncthreads();                             // SYNC 5

    // ---- Phase 6: bin all values; top-2 tree levels cached in registers ----
    const float e1 = s_eytz[1], e2 = s_eytz[2], e3 = s_eytz[3];
    int binreg[IPT];
#pragma unroll
    for (int j = 0; j < 4; ++j) {
        float4 p = xr4[t * 4 + j];
        float vals[4] = {p.x, p.y, p.z, p.w};
#pragma unroll
        for (int c = 0; c < 4; ++c) {
            float val = vals[c];
            bool  p1  = (e1 <= val);
            float ex2 = p1 ? e3 : e2;
            bool  p2  = (ex2 <= val);
            unsigned node = 4u + (p1 ? 2u : 0u) + (p2 ? 1u : 0u);   // depth-3
#pragma unroll
            for (int s = 0; s < 5; ++s)
                node = 2u * node + (s_eytz[node] <= val ? 1u : 0u);
            int b = (int)node - 128;             // count of edges <= val
            binreg[j * 4 + c] = (b > NB - 1) ? (NB - 1) : b;
        }
    }

    // boundary bin (next thread's first element) without smem/barrier
    int nextbin = __shfl_down_sync(0xffffffffu, binreg[0], 1);
    if (lane == 31 && t < NT - 1) {
        float val = xr[t * IPT + IPT];           // L1-hot scalar load
        bool  p1  = (e1 <= val);
        float ex2 = p1 ? e3 : e2;
        bool  p2  = (ex2 <= val);
        unsigned node = 4u + (p1 ? 2u : 0u) + (p2 ? 1u : 0u);
#pragma unroll
        for (int s = 0; s < 5; ++s)
            node = 2u * node + (s_eytz[node] <= val ? 1u : 0u);
        int b = (int)node - 128;
        nextbin = (b > NB - 1) ? (NB - 1) : b;
    }

    // ---- Phase 7: transition histogram (shared atomics) ----
#pragma unroll
    for (int i = 0; i < IPT - 1; ++i)
        atomicAdd(&hist[binreg[i] * NB + binreg[i + 1]], 1u);
    if (t < NT - 1)
        atomicAdd(&hist[binreg[IPT - 1] * NB + nextbin], 1u);
    __syncthreads();                             // SYNC 6

    // ---- Phase 8: normalize + store ----
    const float inv = 1.0f / (float)(L - 1);
    float* __restrict__ outr = out + (size_t)row * NB * NB;
    for (int i = t; i < NB * NB; i += NT)
        outr[i] = (float)hist[i] * inv;
}

extern "C" void kernel_launch(void* const* d_in, const int* in_sizes, int n_in,
                              void* d_out, int out_size)
{
    const float* x = (const float*)d_in[0];
    float* out = (float*)d_out;
    const int rows = in_sizes[0] / L;   // 512*4 = 2048

    cudaFuncSetAttribute(mtf_kernel,
                         cudaFuncAttributeMaxDynamicSharedMemorySize,
                         (int)SMEM_TOTAL);
    mtf_kernel<<<rows, NT, SMEM_TOTAL>>>(x, out);
}

// round 15
// speedup vs baseline: 1.9899x; 1.0129x over previous
#include <cuda_runtime.h>
#include <cuda_bf16.h>
#include <cfloat>

// Problem constants
constexpr int L   = 8192;   // row length
constexpr int NB  = 65;     // bins / quantile edges
constexpr int NT  = 512;    // threads per block
constexpr int IPT = 16;     // items per thread (NT*IPT == L)

// Skewed (padded) addressing: one pad float per 32 -> strided warp accesses
// land on 32 distinct banks instead of few.
__device__ __forceinline__ int PAD(int i) { return i + (i >> 5); }
constexpr int PADL = L + (L >> 5);          // 8448 floats per buffer

// Shared layout: bufA[PADL] | bufB[PADL] | hist[NB*NB]
constexpr size_t BUF_BYTES  = (size_t)PADL * sizeof(float);
constexpr size_t SMEM_TOTAL = 2 * BUF_BYTES + (size_t)NB * NB * sizeof(unsigned);

// ---------------- bitonic (warp sorts 512, 16/thread), templated stages ------
template <int K, int J>
__device__ __forceinline__ void cross_stage_t(float (&v)[IPT], int lane)
{
    const int  lmask   = J >> 4;
    const bool up      = (lane & lmask) == 0;
    const bool asc     = ((lane << 4) & K) == 0;       // hoisted (K>=32)
    const bool keepMin = (asc == up);
#pragma unroll
    for (int i = 0; i < IPT; ++i) {
        float other = __shfl_xor_sync(0xffffffffu, v[i], lmask);
        v[i] = keepMin ? fminf(v[i], other) : fmaxf(v[i], other);
    }
}

template <int K, int J>
__device__ __forceinline__ void inthread_stage_t(float (&v)[IPT], int lane)
{
    bool ascL = true;
    if constexpr (K >= 32)      ascL = (((lane << 4) & K) == 0);
    else if constexpr (K == 16) ascL = ((lane & 1) == 0);
#pragma unroll
    for (int i = 0; i < IPT; ++i) {
        if ((i & J) != 0) continue;                    // compile-time
        const int q = i | J;
        bool asc;
        if constexpr (K <= 8) asc = ((i & K) == 0);    // compile-time
        else                  asc = ascL;              // per-stage predicate
        float a = v[i], b = v[q];
        float mn = fminf(a, b), mx = fmaxf(a, b);
        v[i] = asc ? mn : mx;
        v[q] = asc ? mx : mn;
    }
}

template <int K>
__device__ __forceinline__ void inthread_tail(float (&v)[IPT], int lane)
{
    if constexpr (K >= 16) inthread_stage_t<K, 8>(v, lane);
    if constexpr (K >= 8)  inthread_stage_t<K, 4>(v, lane);
    if constexpr (K >= 4)  inthread_stage_t<K, 2>(v, lane);
    inthread_stage_t<K, 1>(v, lane);
}

__device__ __forceinline__ void warp_bitonic_512(float (&v)[IPT], int lane)
{
    inthread_tail<2>(v, lane);
    inthread_tail<4>(v, lane);
    inthread_tail<8>(v, lane);
    inthread_tail<16>(v, lane);

    cross_stage_t<32, 16>(v, lane);   inthread_tail<32>(v, lane);
    cross_stage_t<64, 32>(v, lane);
    cross_stage_t<64, 16>(v, lane);   inthread_tail<64>(v, lane);
    cross_stage_t<128, 64>(v, lane);
    cross_stage_t<128, 32>(v, lane);
    cross_stage_t<128, 16>(v, lane);  inthread_tail<128>(v, lane);
    cross_stage_t<256, 128>(v, lane);
    cross_stage_t<256, 64>(v, lane);
    cross_stage_t<256, 32>(v, lane);
    cross_stage_t<256, 16>(v, lane);  inthread_tail<256>(v, lane);
    cross_stage_t<512, 256>(v, lane);
    cross_stage_t<512, 128>(v, lane);
    cross_stage_t<512, 64>(v, lane);
    cross_stage_t<512, 32>(v, lane);
    cross_stage_t<512, 16>(v, lane);  inthread_tail<512>(v, lane);
}

// ------------- merge-path round, 2 independent 8-output chains per thread ----
// Fixed-depth branchless partitions (no warp divergence); merge compare relies
// on FLT_MAX stream sentinels (FLT_MAX cannot occur in the data).
template <int R>
__device__ __forceinline__ void merge_round(const float* __restrict__ src,
                                            float* __restrict__ dst, int t)
{
    constexpr int STEPS = (R == 512) ? 10 : (R == 1024) ? 11 : 12;
    const int pairlen = R << 1;
    const int g0 = t * 8;            // chain 0 output start
    const int g1 = (L / 2) + t * 8;  // chain 1 output start (4096 % pairlen == 0)

    const int pb0 = (g0 / pairlen) * pairlen, o0 = g0 & (pairlen - 1);
    const int pb1 = (g1 / pairlen) * pairlen, o1 = g1 & (pairlen - 1);

    int lo0 = (o0 - R > 0) ? o0 - R : 0;
    int hi0 = (o0 < R) ? o0 : R;
    int lo1 = (o1 - R > 0) ? o1 - R : 0;
    int hi1 = (o1 < R) ? o1 : R;
#pragma unroll
    for (int s = 0; s < STEPS; ++s) {
        int mid0 = (lo0 + hi0) >> 1;
        int mid1 = (lo1 + hi1) >> 1;
        bool c0 = (src[PAD(pb0 + mid0)] <= src[PAD(pb0 + R + o0 - 1 - mid0)])
                  && (lo0 < hi0);
        bool c1 = (src[PAD(pb1 + mid1)] <= src[PAD(pb1 + R + o1 - 1 - mid1)])
                  && (lo1 < hi1);
        lo0 = c0 ? mid0 + 1 : lo0;   hi0 = c0 ? hi0 : mid0;
        lo1 = c1 ? mid1 + 1 : lo1;   hi1 = c1 ? hi1 : mid1;
    }
    int a0 = lo0, b0 = o0 - lo0;
    int a1 = lo1, b1 = o1 - lo1;

    float av0 = (a0 < R) ? src[PAD(pb0 + a0)]     : FLT_MAX;
    float bv0 = (b0 < R) ? src[PAD(pb0 + R + b0)] : FLT_MAX;
    float av1 = (a1 < R) ? src[PAD(pb1 + a1)]     : FLT_MAX;
    float bv1 = (b1 < R) ? src[PAD(pb1 + R + b1)] : FLT_MAX;
#pragma unroll
    for (int i = 0; i < 8; ++i) {
        bool tA0 = (av0 <= bv0);     // exhausted side holds FLT_MAX
        bool tA1 = (av1 <= bv1);
        float ov0 = tA0 ? av0 : bv0;
        float ov1 = tA1 ? av1 : bv1;
        if (tA0) { ++a0; av0 = (a0 < R) ? src[PAD(pb0 + a0)]     : FLT_MAX; }
        else     { ++b0; bv0 = (b0 < R) ? src[PAD(pb0 + R + b0)] : FLT_MAX; }
        if (tA1) { ++a1; av1 = (a1 < R) ? src[PAD(pb1 + a1)]     : FLT_MAX; }
        else     { ++b1; bv1 = (b1 < R) ? src[PAD(pb1 + R + b1)] : FLT_MAX; }
        dst[PAD(g0 + i)] = ov0;
        dst[PAD(g1 + i)] = ov1;
    }
}

// k-th smallest (0-indexed) of the union of two sorted runs in the same padded
// buffer at bases Ab, Bb, each length n.
__device__ __forceinline__ float select2(const float* __restrict__ buf,
                                         int Ab, int Bb, int n, int k)
{
    int ilo = (k + 1 - n > 0) ? (k + 1 - n) : 0;
    int ihi = (k + 1 < n) ? (k + 1) : n;
    for (;;) {
        int i = (ilo + ihi) >> 1;
        int j = k + 1 - i;
        float Aim1 = (i > 0) ? buf[PAD(Ab + i - 1)] : -FLT_MAX;
        float Ai   = (i < n) ? buf[PAD(Ab + i)]     :  FLT_MAX;
        float Bjm1 = (j > 0) ? buf[PAD(Bb + j - 1)] : -FLT_MAX;
        float Bj   = (j < n) ? buf[PAD(Bb + j)]     :  FLT_MAX;
        if (Aim1 > Bj)       ihi = i - 1;
        else if (Bjm1 > Ai)  ilo = i + 1;
        else return fmaxf(Aim1, Bjm1);
    }
}

__global__ __launch_bounds__(NT, 2) void mtf_kernel(const float* __restrict__ x,
                                                    float* __restrict__ out)
{
    extern __shared__ char smem_raw[];
    float*    bufA = reinterpret_cast<float*>(smem_raw);
    float*    bufB = reinterpret_cast<float*>(smem_raw + BUF_BYTES);
    unsigned* hist = reinterpret_cast<unsigned*>(smem_raw + 2 * BUF_BYTES);

    __shared__ float s_eytz[128];    // BFS layout of 127 padded edges
    __shared__ int   s_wmin[16], s_wmax[16], s_wneg[16];
    __shared__ int   s_m, s_neg;

    const int row  = blockIdx.x;
    const int t    = threadIdx.x;
    const int w    = t >> 5;
    const int lane = t & 31;

    const float* __restrict__ xr = x + (size_t)row * L;
    const float4* __restrict__ xr4 = reinterpret_cast<const float4*>(xr);

    // ---- Phase 1: load raw row, mask-based scan (FSETP+LOP, no SEL chains) --
    float v[IPT];
    unsigned nzmask = 0u;
    int lneg = 0;
#pragma unroll
    for (int j = 0; j < 4; ++j) {
        float4 p = xr4[t * 4 + j];
        v[j * 4 + 0] = p.x; v[j * 4 + 1] = p.y;
        v[j * 4 + 2] = p.z; v[j * 4 + 3] = p.w;
#pragma unroll
        for (int c = 0; c < 4; ++c) {
            float val = v[j * 4 + c];
            if (val != 0.0f) nzmask |= (1u << (j * 4 + c));
            if (val <  0.0f) ++lneg;
        }
    }
    int lmin = nzmask ? (t * IPT + __ffs(nzmask) - 1) : L;
    int lmax = nzmask ? (t * IPT + 31 - __clz(nzmask)) : -1;
    lmin = __reduce_min_sync(0xffffffffu, lmin);
    lmax = __reduce_max_sync(0xffffffffu, lmax);
    lneg = __reduce_add_sync(0xffffffffu, lneg);
    if (lane == 0) { s_wmin[w] = lmin; s_wmax[w] = lmax; s_wneg[w] = lneg; }

    // ---- Phase 2: bitonic sort RAW values (ALU/SHFL only, no mask pass) ----
    warp_bitonic_512(v, lane);
#pragma unroll
    for (int i = 0; i < IPT; ++i) bufA[PAD(t * IPT + i)] = v[i];   // conflict-free

    // shadow work before the barrier: vectorized hist zeroing + eytz prefill
    {
        uint4 z4 = make_uint4(0u, 0u, 0u, 0u);
        uint4* h4 = reinterpret_cast<uint4*>(hist);
        for (int i = t; i < (NB * NB) / 4; i += NT) h4[i] = z4;   // 1056 uint4
        if (t == 0) hist[NB * NB - 1] = 0u;                        // tail word
        if (t >= 1 && t < 128) s_eytz[t] = FLT_MAX;                // pad nodes
    }
    __syncthreads();                             // SYNC 1

    // ---- Phase 3: warp 0 finalizes the scan while everyone merges ----
    if (w == 0 && lane < 16) {
        int a = s_wmin[lane], b = s_wmax[lane], c = s_wneg[lane];
        a = __reduce_min_sync(0x0000ffffu, a);
        b = __reduce_max_sync(0x0000ffffu, b);
        c = __reduce_add_sync(0x0000ffffu, c);
        if (lane == 0) {
            s_m   = (b >= 0) ? (b - a + 1) : 0;
            s_neg = c;
        }
    }

    // ---- Phase 4: three merge rounds: 512 -> 1024 -> 2048 -> 4096 ----
    merge_round<512>(bufA, bufB, t);  __syncthreads();   // SYNC 2
    merge_round<1024>(bufB, bufA, t); __syncthreads();   // SYNC 3
    merge_round<2048>(bufA, bufB, t); __syncthreads();   // SYNC 4
    // two sorted runs of 4096 at padded bases 0 and 4096 in bufB

    // hoisted Phase-6 reloads: independent of edges; latency hides under
    // select2 (t<130) or the SYNC-5 barrier wait (everyone else)
    float4 r0 = xr4[t * 4 + 0];
    float4 r1 = xr4[t * 4 + 1];
    float4 r2 = xr4[t * 4 + 2];
    float4 r3 = xr4[t * 4 + 3];

    // ---- Phase 5: distributed quantile selection, ONE select2 per thread.
    // Thread t<130: edge e = t>>1, which = t&1 (0 -> lo rank, 1 -> hi rank).
    // Partner values combine via shfl (pairs are intra-warp: 2e is even).
    // Combiner writes the edge straight into its Eytzinger node.
    if (t < 130) {
        const int e     = t >> 1;
        const int which = t & 1;
        const int m     = s_m;
        float q = 0.0f;
        float frac = 0.0f;
        float val  = 0.0f;
        int   samerank = 1;
        if (m > 0) {
            const float step = 1.0f / 65.0f;
            float qlev = (float)e * step;
            float pos  = qlev * (float)(m - 1);
            int   lo   = (int)floorf(pos);
            int   hi   = (int)ceilf(pos);
            frac = pos - (float)lo;
            samerank = (hi == lo);
            int r    = which ? hi : lo;
            int neg  = s_neg, zout = L - m;
            int k    = (r < neg) ? r : r + zout;
            val = select2(bufB, 0, 4096, 4096, k);
        }
        const unsigned shmask = (w < 4) ? 0xffffffffu : 0x3u;  // warp 4: lanes 0,1
        float vhi = __shfl_down_sync(shmask, val, 1);
        if (which == 0) {
            if (m > 0) {
                float vlo = val;
                if (samerank) vhi = vlo;
                q = vlo + frac * (vhi - vlo);
            }
            // inverse BFS mapping: e -> tree node
            int z    = __ffs(e + 1) - 1;         // trailing zeros of (e+1)
            int d    = 6 - z;
            int jj   = (((e + 1) >> z) - 1) >> 1;
            s_eytz[(1 << d) + jj] = q;
        }
    }
    __syncthreads();                             // SYNC 5

    // ---- Phase 6: bin all values; top-2 tree levels cached in registers ----
    const float e1 = s_eytz[1], e2 = s_eytz[2], e3 = s_eytz[3];
    int binreg[IPT];
    {
        float vals[IPT] = {r0.x, r0.y, r0.z, r0.w, r1.x, r1.y, r1.z, r1.w,
                           r2.x, r2.y, r2.z, r2.w, r3.x, r3.y, r3.z, r3.w};
#pragma unroll
        for (int c = 0; c < IPT; ++c) {
            float val = vals[c];
            bool  p1  = (e1 <= val);
            float ex2 = p1 ? e3 : e2;
            bool  p2  = (ex2 <= val);
            unsigned node = 4u + (p1 ? 2u : 0u) + (p2 ? 1u : 0u);   // depth-3
#pragma unroll
            for (int s = 0; s < 5; ++s)
                node = 2u * node + (s_eytz[node] <= val ? 1u : 0u);
            int b = (int)node - 128;             // count of edges <= val
            binreg[c] = (b > NB - 1) ? (NB - 1) : b;
        }
    }

    // boundary bin (next thread's first element) without smem/barrier
    int nextbin = __shfl_down_sync(0xffffffffu, binreg[0], 1);
    if (lane == 31 && t < NT - 1) {
        float val = xr[t * IPT + IPT];           // L1-hot scalar load
        bool  p1  = (e1 <= val);
        float ex2 = p1 ? e3 : e2;
        bool  p2  = (ex2 <= val);
        unsigned node = 4u + (p1 ? 2u : 0u) + (p2 ? 1u : 0u);
#pragma unroll
        for (int s = 0; s < 5; ++s)
            node = 2u * node + (s_eytz[node] <= val ? 1u : 0u);
        int b = (int)node - 128;
        nextbin = (b > NB - 1) ? (NB - 1) : b;
    }

    // ---- Phase 7: transition histogram (shared atomics) ----
#pragma unroll
    for (int i = 0; i < IPT - 1; ++i)
        atomicAdd(&hist[binreg[i] * NB + binreg[i + 1]], 1u);
    if (t < NT - 1)
        atomicAdd(&hist[binreg[IPT - 1] * NB + nextbin], 1u);
    __syncthreads();                             // SYNC 6

    // ---- Phase 8: normalize + store.
    // hist is 16B-aligned -> vectorized LDS.128 reads; but out+row*4225 floats
    // is only 4B-aligned for odd rows -> SCALAR STG.32 stores (alignment-safe).
    const float inv = 1.0f / (float)(L - 1);
    float* __restrict__ outr = out + (size_t)row * NB * NB;
    const uint4* __restrict__ h4 = reinterpret_cast<const uint4*>(hist);
    for (int i = t; i < (NB * NB) / 4; i += NT) {        // 1056 uint4
        uint4 hv = h4[i];
        int o = i * 4;
        outr[o + 0] = (float)hv.x * inv;
        outr[o + 1] = (float)hv.y * inv;
        outr[o + 2] = (float)hv.z * inv;
        outr[o + 3] = (float)hv.w * inv;
    }
    if (t == 0) outr[NB * NB - 1] = (float)hist[NB * NB - 1] * inv;  // tail
}

extern "C" void kernel_launch(void* const* d_in, const int* in_sizes, int n_in,
                              void* d_out, int out_size)
{
    const float* x = (const float*)d_in[0];
    float* out = (float*)d_out;
    const int rows = in_sizes[0] / L;   // 512*4 = 2048

    cudaFuncSetAttribute(mtf_kernel,
                         cudaFuncAttributeMaxDynamicSharedMemorySize,
                         (int)SMEM_TOTAL);
    mtf_kernel<<<rows, NT, SMEM_TOTAL>>>(x, out);
}

// round 16
// speedup vs baseline: 2.1411x; 1.0760x over previous
#include <cuda_runtime.h>
#include <cuda_bf16.h>
#include <cfloat>

// Problem constants
constexpr int L   = 8192;   // row length
constexpr int NB  = 65;     // bins / quantile edges
constexpr int NT  = 512;    // threads per block
constexpr int IPT = 16;     // items per thread (NT*IPT == L)
constexpr int GAP = 8;      // FLT_MAX sentinel slots after every run

// Skewed (padded) addressing: one pad float per 32 -> strided warp accesses
// land on (nearly) distinct banks.
__device__ __forceinline__ int PAD(int i) { return i + (i >> 5); }

// Gapped extents: initial 16 runs * (512+8) = 8320 is the max.
constexpr int MAXG = 16 * (512 + GAP);            // 8320
constexpr int PADL = MAXG + (MAXG >> 5);          // 8580 floats per buffer

// Shared layout: bufA[PADL] | bufB[PADL] | hist[NB*NB]
constexpr size_t BUF_BYTES  = (size_t)PADL * sizeof(float);
constexpr size_t SMEM_TOTAL = 2 * BUF_BYTES + (size_t)NB * NB * sizeof(unsigned);

// ---------------- bitonic (warp sorts 512, 16/thread), templated stages ------
template <int K, int J>
__device__ __forceinline__ void cross_stage_t(float (&v)[IPT], int lane)
{
    const int  lmask   = J >> 4;
    const bool up      = (lane & lmask) == 0;
    const bool asc     = ((lane << 4) & K) == 0;       // hoisted (K>=32)
    const bool keepMin = (asc == up);
#pragma unroll
    for (int i = 0; i < IPT; ++i) {
        float other = __shfl_xor_sync(0xffffffffu, v[i], lmask);
        v[i] = keepMin ? fminf(v[i], other) : fmaxf(v[i], other);
    }
}

template <int K, int J>
__device__ __forceinline__ void inthread_stage_t(float (&v)[IPT], int lane)
{
    bool ascL = true;
    if constexpr (K >= 32)      ascL = (((lane << 4) & K) == 0);
    else if constexpr (K == 16) ascL = ((lane & 1) == 0);
#pragma unroll
    for (int i = 0; i < IPT; ++i) {
        if ((i & J) != 0) continue;                    // compile-time
        const int q = i | J;
        bool asc;
        if constexpr (K <= 8) asc = ((i & K) == 0);    // compile-time
        else                  asc = ascL;              // per-stage predicate
        float a = v[i], b = v[q];
        float mn = fminf(a, b), mx = fmaxf(a, b);
        v[i] = asc ? mn : mx;
        v[q] = asc ? mx : mn;
    }
}

template <int K>
__device__ __forceinline__ void inthread_tail(float (&v)[IPT], int lane)
{
    if constexpr (K >= 16) inthread_stage_t<K, 8>(v, lane);
    if constexpr (K >= 8)  inthread_stage_t<K, 4>(v, lane);
    if constexpr (K >= 4)  inthread_stage_t<K, 2>(v, lane);
    inthread_stage_t<K, 1>(v, lane);
}

__device__ __forceinline__ void warp_bitonic_512(float (&v)[IPT], int lane)
{
    inthread_tail<2>(v, lane);
    inthread_tail<4>(v, lane);
    inthread_tail<8>(v, lane);
    inthread_tail<16>(v, lane);

    cross_stage_t<32, 16>(v, lane);   inthread_tail<32>(v, lane);
    cross_stage_t<64, 32>(v, lane);
    cross_stage_t<64, 16>(v, lane);   inthread_tail<64>(v, lane);
    cross_stage_t<128, 64>(v, lane);
    cross_stage_t<128, 32>(v, lane);
    cross_stage_t<128, 16>(v, lane);  inthread_tail<128>(v, lane);
    cross_stage_t<256, 128>(v, lane);
    cross_stage_t<256, 64>(v, lane);
    cross_stage_t<256, 32>(v, lane);
    cross_stage_t<256, 16>(v, lane);  inthread_tail<256>(v, lane);
    cross_stage_t<512, 256>(v, lane);
    cross_stage_t<512, 128>(v, lane);
    cross_stage_t<512, 64>(v, lane);
    cross_stage_t<512, 32>(v, lane);
    cross_stage_t<512, 16>(v, lane);  inthread_tail<512>(v, lane);
}

// ------------- merge-path round, 2 independent 8-output chains per thread ----
// Runs stored with stride R+GAP; gaps hold FLT_MAX sentinels so stream reads
// need NO bounds checks (FLT_MAX cannot occur in the data; a stream presenting
// a sentinel simply loses every compare until the segment completes).
template <int R>
__device__ __forceinline__ void merge_round(const float* __restrict__ src,
                                            float* __restrict__ dst, int t)
{
    constexpr int STEPS = (R == 512) ? 10 : (R == 1024) ? 11 : 12;
    constexpr int INS   = R + GAP;
    constexpr int OUTS  = 2 * R + GAP;
    const int pairlen = R << 1;

    const int g0 = t * 8;            // chain 0 logical output start
    const int g1 = (L / 2) + t * 8;  // chain 1 logical output start

    const int p0 = g0 / pairlen, o0 = g0 & (pairlen - 1);
    const int p1 = g1 / pairlen, o1 = g1 & (pairlen - 1);
    const int A0 = (2 * p0) * INS, B0 = A0 + INS;
    const int A1 = (2 * p1) * INS, B1 = A1 + INS;

    int lo0 = (o0 - R > 0) ? o0 - R : 0;
    int hi0 = (o0 < R) ? o0 : R;
    int lo1 = (o1 - R > 0) ? o1 - R : 0;
    int hi1 = (o1 < R) ? o1 : R;
#pragma unroll
    for (int s = 0; s < STEPS; ++s) {
        int mid0 = (lo0 + hi0) >> 1;
        int mid1 = (lo1 + hi1) >> 1;
        bool c0 = (src[PAD(A0 + mid0)] <= src[PAD(B0 + o0 - 1 - mid0)])
                  && (lo0 < hi0);
        bool c1 = (src[PAD(A1 + mid1)] <= src[PAD(B1 + o1 - 1 - mid1)])
                  && (lo1 < hi1);
        lo0 = c0 ? mid0 + 1 : lo0;   hi0 = c0 ? hi0 : mid0;
        lo1 = c1 ? mid1 + 1 : lo1;   hi1 = c1 ? hi1 : mid1;
    }
    int a0 = lo0, b0 = o0 - lo0;
    int a1 = lo1, b1 = o1 - lo1;

    float av0 = src[PAD(A0 + a0)];           // unguarded: gaps are sentinels
    float bv0 = src[PAD(B0 + b0)];
    float av1 = src[PAD(A1 + a1)];
    float bv1 = src[PAD(B1 + b1)];
    const int ob0 = p0 * OUTS + o0;
    const int ob1 = p1 * OUTS + o1;
#pragma unroll
    for (int i = 0; i < 8; ++i) {
        bool tA0 = (av0 <= bv0);
        bool tA1 = (av1 <= bv1);
        float ov0 = tA0 ? av0 : bv0;
        float ov1 = tA1 ? av1 : bv1;
        if (tA0) { ++a0; av0 = src[PAD(A0 + a0)]; }
        else     { ++b0; bv0 = src[PAD(B0 + b0)]; }
        if (tA1) { ++a1; av1 = src[PAD(A1 + a1)]; }
        else     { ++b1; bv1 = src[PAD(B1 + b1)]; }
        dst[PAD(ob0 + i)] = ov0;
        dst[PAD(ob1 + i)] = ov1;
    }

    // fill this round's OUTPUT gap sentinels (read unguarded next round)
    if constexpr (R < 2048) {
        constexpr int NRUNS_OUT = L / (2 * R);
        if (t < NRUNS_OUT * GAP)
            dst[PAD((t >> 3) * OUTS + 2 * R + (t & 7))] = FLT_MAX;
    }
}

// k-th smallest (0-indexed) of the union of two sorted runs in the same padded
// buffer at bases Ab, Bb, each length n.  (Guarded — only 130 threads run it.)
__device__ __forceinline__ float select2(const float* __restrict__ buf,
                                         int Ab, int Bb, int n, int k)
{
    int ilo = (k + 1 - n > 0) ? (k + 1 - n) : 0;
    int ihi = (k + 1 < n) ? (k + 1) : n;
    for (;;) {
        int i = (ilo + ihi) >> 1;
        int j = k + 1 - i;
        float Aim1 = (i > 0) ? buf[PAD(Ab + i - 1)] : -FLT_MAX;
        float Ai   = (i < n) ? buf[PAD(Ab + i)]     :  FLT_MAX;
        float Bjm1 = (j > 0) ? buf[PAD(Bb + j - 1)] : -FLT_MAX;
        float Bj   = (j < n) ? buf[PAD(Bb + j)]     :  FLT_MAX;
        if (Aim1 > Bj)       ihi = i - 1;
        else if (Bjm1 > Ai)  ilo = i + 1;
        else return fmaxf(Aim1, Bjm1);
    }
}

__global__ __launch_bounds__(NT, 2) void mtf_kernel(const float* __restrict__ x,
                                                    float* __restrict__ out)
{
    extern __shared__ char smem_raw[];
    float*    bufA = reinterpret_cast<float*>(smem_raw);
    float*    bufB = reinterpret_cast<float*>(smem_raw + BUF_BYTES);
    unsigned* hist = reinterpret_cast<unsigned*>(smem_raw + 2 * BUF_BYTES);

    __shared__ float s_eytz[128];    // BFS layout of 127 padded edges
    __shared__ int   s_wmin[16], s_wmax[16], s_wneg[16];
    __shared__ int   s_m, s_neg;

    const int row  = blockIdx.x;
    const int t    = threadIdx.x;
    const int w    = t >> 5;
    const int lane = t & 31;

    const float* __restrict__ xr = x + (size_t)row * L;
    const float4* __restrict__ xr4 = reinterpret_cast<const float4*>(xr);

    // ---- Phase 1: load raw row, mask-based scan (FSETP+LOP, no SEL chains) --
    float v[IPT];
    unsigned nzmask = 0u;
    int lneg = 0;
#pragma unroll
    for (int j = 0; j < 4; ++j) {
        float4 p = xr4[t * 4 + j];
        v[j * 4 + 0] = p.x; v[j * 4 + 1] = p.y;
        v[j * 4 + 2] = p.z; v[j * 4 + 3] = p.w;
#pragma unroll
        for (int c = 0; c < 4; ++c) {
            float val = v[j * 4 + c];
            if (val != 0.0f) nzmask |= (1u << (j * 4 + c));
            if (val <  0.0f) ++lneg;
        }
    }
    int lmin = nzmask ? (t * IPT + __ffs(nzmask) - 1) : L;
    int lmax = nzmask ? (t * IPT + 31 - __clz(nzmask)) : -1;
    lmin = __reduce_min_sync(0xffffffffu, lmin);
    lmax = __reduce_max_sync(0xffffffffu, lmax);
    lneg = __reduce_add_sync(0xffffffffu, lneg);
    if (lane == 0) { s_wmin[w] = lmin; s_wmax[w] = lmax; s_wneg[w] = lneg; }

    // ---- Phase 2: bitonic sort RAW values; stage runs at stride 520 ----
    warp_bitonic_512(v, lane);
#pragma unroll
    for (int i = 0; i < IPT; ++i)
        bufA[PAD(w * (512 + GAP) + lane * IPT + i)] = v[i];

    // shadow work before the barrier: staging gap sentinels, hist zero, eytz pad
    {
        if (t < 16 * GAP)   // 128 threads: one sentinel each
            bufA[PAD((t >> 3) * (512 + GAP) + 512 + (t & 7))] = FLT_MAX;
        uint4 z4 = make_uint4(0u, 0u, 0u, 0u);
        uint4* h4 = reinterpret_cast<uint4*>(hist);
        for (int i = t; i < (NB * NB) / 4; i += NT) h4[i] = z4;   // 1056 uint4
        if (t == 0) hist[NB * NB - 1] = 0u;                        // tail word
        if (t >= 1 && t < 128) s_eytz[t] = FLT_MAX;                // pad nodes
    }
    __syncthreads();                             // SYNC 1

    // ---- Phase 3: warp 0 finalizes the scan while everyone merges ----
    if (w == 0 && lane < 16) {
        int a = s_wmin[lane], b = s_wmax[lane], c = s_wneg[lane];
        a = __reduce_min_sync(0x0000ffffu, a);
        b = __reduce_max_sync(0x0000ffffu, b);
        c = __reduce_add_sync(0x0000ffffu, c);
        if (lane == 0) {
            s_m   = (b >= 0) ? (b - a + 1) : 0;
            s_neg = c;
        }
    }

    // ---- Phase 4: three merge rounds: 512 -> 1024 -> 2048 -> 4096 ----
    merge_round<512>(bufA, bufB, t);  __syncthreads();   // SYNC 2
    merge_round<1024>(bufB, bufA, t); __syncthreads();   // SYNC 3
    merge_round<2048>(bufA, bufB, t); __syncthreads();   // SYNC 4
    // two sorted runs of 4096 at gapped bases 0 and 4104 in bufB

    // hoisted Phase-6 reloads: latency hides under select2 / SYNC-5 wait
    float4 r0 = xr4[t * 4 + 0];
    float4 r1 = xr4[t * 4 + 1];
    float4 r2 = xr4[t * 4 + 2];
    float4 r3 = xr4[t * 4 + 3];

    // ---- Phase 5: distributed quantile selection, ONE select2 per thread ----
    if (t < 130) {
        const int e     = t >> 1;
        const int which = t & 1;
        const int m     = s_m;
        float q = 0.0f;
        float frac = 0.0f;
        float val  = 0.0f;
        int   samerank = 1;
        if (m > 0) {
            const float step = 1.0f / 65.0f;
            float qlev = (float)e * step;
            float pos  = qlev * (float)(m - 1);
            int   lo   = (int)floorf(pos);
            int   hi   = (int)ceilf(pos);
            frac = pos - (float)lo;
            samerank = (hi == lo);
            int r    = which ? hi : lo;
            int neg  = s_neg, zout = L - m;
            int k    = (r < neg) ? r : r + zout;
            val = select2(bufB, 0, 2 * 2048 + GAP, 4096, k);
        }
        const unsigned shmask = (w < 4) ? 0xffffffffu : 0x3u;  // warp 4: lanes 0,1
        float vhi = __shfl_down_sync(shmask, val, 1);
        if (which == 0) {
            if (m > 0) {
                float vlo = val;
                if (samerank) vhi = vlo;
                q = vlo + frac * (vhi - vlo);
            }
            // inverse BFS mapping: e -> tree node
            int z    = __ffs(e + 1) - 1;         // trailing zeros of (e+1)
            int d    = 6 - z;
            int jj   = (((e + 1) >> z) - 1) >> 1;
            s_eytz[(1 << d) + jj] = q;
        }
    }
    __syncthreads();                             // SYNC 5

    // ---- Phase 6: bin all values; top-2 tree levels cached in registers ----
    const float e1 = s_eytz[1], e2 = s_eytz[2], e3 = s_eytz[3];
    int binreg[IPT];
    {
        float vals[IPT] = {r0.x, r0.y, r0.z, r0.w, r1.x, r1.y, r1.z, r1.w,
                           r2.x, r2.y, r2.z, r2.w, r3.x, r3.y, r3.z, r3.w};
#pragma unroll
        for (int c = 0; c < IPT; ++c) {
            float val = vals[c];
            bool  p1  = (e1 <= val);
            float ex2 = p1 ? e3 : e2;
            bool  p2  = (ex2 <= val);
            unsigned node = 4u + (p1 ? 2u : 0u) + (p2 ? 1u : 0u);   // depth-3
#pragma unroll
            for (int s = 0; s < 5; ++s)
                node = 2u * node + (s_eytz[node] <= val ? 1u : 0u);
            int b = (int)node - 128;             // count of edges <= val
            binreg[c] = (b > NB - 1) ? (NB - 1) : b;
        }
    }

    // boundary bin (next thread's first element) without smem/barrier
    int nextbin = __shfl_down_sync(0xffffffffu, binreg[0], 1);
    if (lane == 31 && t < NT - 1) {
        float val = xr[t * IPT + IPT];           // L1-hot scalar load
        bool  p1  = (e1 <= val);
        float ex2 = p1 ? e3 : e2;
        bool  p2  = (ex2 <= val);
        unsigned node = 4u + (p1 ? 2u : 0u) + (p2 ? 1u : 0u);
#pragma unroll
        for (int s = 0; s < 5; ++s)
            node = 2u * node + (s_eytz[node] <= val ? 1u : 0u);
        int b = (int)node - 128;
        nextbin = (b > NB - 1) ? (NB - 1) : b;
    }

    // ---- Phase 7: transition histogram (shared atomics) ----
#pragma unroll
    for (int i = 0; i < IPT - 1; ++i)
        atomicAdd(&hist[binreg[i] * NB + binreg[i + 1]], 1u);
    if (t < NT - 1)
        atomicAdd(&hist[binreg[IPT - 1] * NB + nextbin], 1u);
    __syncthreads();                             // SYNC 6

    // ---- Phase 8: normalize + store (LDS.128 reads, scalar STG for alignment)
    const float inv = 1.0f / (float)(L - 1);
    float* __restrict__ outr = out + (size_t)row * NB * NB;
    const uint4* __restrict__ h4 = reinterpret_cast<const uint4*>(hist);
    for (int i = t; i < (NB * NB) / 4; i += NT) {        // 1056 uint4
        uint4 hv = h4[i];
        int o = i * 4;
        outr[o + 0] = (float)hv.x * inv;
        outr[o + 1] = (float)hv.y * inv;
        outr[o + 2] = (float)hv.z * inv;
        outr[o + 3] = (float)hv.w * inv;
    }
    if (t == 0) outr[NB * NB - 1] = (float)hist[NB * NB - 1] * inv;  // tail
}

extern "C" void kernel_launch(void* const* d_in, const int* in_sizes, int n_in,
                              void* d_out, int out_size)
{
    const float* x = (const float*)d_in[0];
    float* out = (float*)d_out;
    const int rows = in_sizes[0] / L;   // 512*4 = 2048

    cudaFuncSetAttribute(mtf_kernel,
                         cudaFuncAttributeMaxDynamicSharedMemorySize,
                         (int)SMEM_TOTAL);
    mtf_kernel<<<rows, NT, SMEM_TOTAL>>>(x, out);
}